// round 9
// baseline (speedup 1.0000x reference)
#include <cuda_runtime.h>
#include <cuda_bf16.h>
#include <cstdint>

// ---------------------------------------------------------------------------
// BarrierNet on GB300, round 9: small-CTA concurrency.
//   4 warps / 64 rows per CTA, 4 CTAs/SM (4 independent barrier domains).
//   Per-warp work identical to R3 (32r x 64c tile, bf16 m16n8k16 mma.sync).
//   Single weight buffer cp.async'd from pre-packed bf16 blobs (R3-style),
//   fc1 recomputed for path 2, head weights read from global (L1-resident).
// ---------------------------------------------------------------------------

#define THREADS 128
#define ROWS_PER_CTA 64
#define STRB 136            // bf16 elems per smem row -> bank permutation
#define ROWB (STRB * 2)     // 272 bytes per row
#define WMAT_BYTES 34816    // 128*272
#define WMAT_CHUNKS (WMAT_BYTES / 16)   // 2176

// byte offsets into dynamic smem (total 55888 -> 4 CTAs/SM)
#define OFF_W    0                      // staged weight matrix (34816)
#define OFF_ACT  34816                  // 64 x 272 activations (17408)
#define OFF_B4   52224                  // 4 x 128 f32 biases (2048)
#define OFF_X    54272                  // 64*6 f32 (1536)
#define OFF_SML  55808                  // 17 f32: b31[0..2] b32[3..4] std[5..10] mean[11..16]
#define SMEM_BYTES 55888

__device__ __align__(16) unsigned char g_wmat[4][WMAT_BYTES];
__device__ float g_wbias[4][128];

__device__ __forceinline__ uint32_t smem_u32(const void* p) {
    uint32_t a;
    asm("{ .reg .u64 t; cvta.to.shared.u64 t, %1; cvt.u32.u64 %0, t; }"
        : "=r"(a) : "l"(p));
    return a;
}

__device__ __forceinline__ void ldsm4(uint32_t& r0, uint32_t& r1, uint32_t& r2, uint32_t& r3,
                                      uint32_t addr) {
    asm volatile("ldmatrix.sync.aligned.m8n8.x4.shared.b16 {%0,%1,%2,%3}, [%4];"
                 : "=r"(r0), "=r"(r1), "=r"(r2), "=r"(r3) : "r"(addr));
}

__device__ __forceinline__ void mma_bf16(float& c0, float& c1, float& c2, float& c3,
                                         uint32_t a0, uint32_t a1, uint32_t a2, uint32_t a3,
                                         uint32_t b0, uint32_t b1) {
    asm volatile(
        "mma.sync.aligned.m16n8k16.row.col.f32.bf16.bf16.f32 "
        "{%0,%1,%2,%3}, {%4,%5,%6,%7}, {%8,%9}, {%0,%1,%2,%3};\n"
        : "+f"(c0), "+f"(c1), "+f"(c2), "+f"(c3)
        : "r"(a0), "r"(a1), "r"(a2), "r"(a3), "r"(b0), "r"(b1));
}

__device__ __forceinline__ uint32_t pack_bf2(float lo, float hi) {
    __nv_bfloat162 h = __floats2bfloat162_rn(lo, hi);
    return *reinterpret_cast<uint32_t*>(&h);
}
__device__ __forceinline__ float tanh_fast(float x) {
    asm("tanh.approx.f32 %0, %0;" : "+f"(x));
    return x;
}

// ---------------- prep kernel: fp32 weights -> padded bf16 rows + biases ----
__global__ void prep_weights(const float* __restrict__ w21, const float* __restrict__ b21,
                             const float* __restrict__ wm1, const float* __restrict__ bm1,
                             const float* __restrict__ w22, const float* __restrict__ b22,
                             const float* __restrict__ wm2, const float* __restrict__ bm2) {
    const float* W[4]  = {w21, wm1, w22, wm2};
    const float* Bv[4] = {b21, bm1, b22, bm2};
    int m = blockIdx.x;
    unsigned char* dst = g_wmat[m];
    const float* src = W[m];
    for (int i = threadIdx.x; i < 128 * 68; i += blockDim.x) {
        int r = i / 68, p = i % 68;
        uint32_t val = 0;
        if (p < 64) {
            float2 v = reinterpret_cast<const float2*>(src)[r * 64 + p];
            val = pack_bf2(v.x, v.y);
        }
        reinterpret_cast<uint32_t*>(dst + r * ROWB)[p] = val;
    }
    if (threadIdx.x < 128) g_wbias[m][threadIdx.x] = Bv[m][threadIdx.x];
}

// ---------------- cp.async weight staging (2176 x 16B) ----------------------
__device__ __forceinline__ void cp_issue(char* sb, int midx, int tid) {
    uint32_t wbase = smem_u32(sb) + OFF_W;
    const unsigned char* g = g_wmat[midx];
    #pragma unroll
    for (int it = 0; it < 17; ++it) {
        int i = tid + it * THREADS;
        if (i < WMAT_CHUNKS) {
            asm volatile("cp.async.cg.shared.global [%0], [%1], 16;"
                         :: "r"(wbase + i * 16),
                            "l"(__cvta_generic_to_global(g + i * 16)));
        }
    }
    asm volatile("cp.async.commit_group;");
}

__device__ __forceinline__ void cp_wait_sync() {
    asm volatile("cp.async.wait_group 0;");
    __syncthreads();
}

// ---------------- fc1 (K=6) + tanh -> ACT (bf16), weights from global -------
__device__ __forceinline__ void fc1_to_act(char* sb, const float* __restrict__ fc1_w,
                                           const float* __restrict__ fc1_b,
                                           const float* __restrict__ xs, int tid) {
    const int cp2 = tid & 63;          // column pair 0..63
    const int rh  = tid >> 6;          // row half 0..1
    const int c0 = 2 * cp2;
    const float* wA = fc1_w + c0 * 6;
    const float* wB = wA + 6;
    float wa0 = wA[0], wa1 = wA[1], wa2 = wA[2], wa3 = wA[3], wa4 = wA[4], wa5 = wA[5];
    float wb0 = wB[0], wb1 = wB[1], wb2 = wB[2], wb3 = wB[3], wb4 = wB[4], wb5 = wB[5];
    float ba = fc1_b[c0], bb = fc1_b[c0 + 1];
    #pragma unroll 8
    for (int rr = 0; rr < 32; ++rr) {
        int row = rh * 32 + rr;
        const float* xr = &xs[row * 6];
        float x0v = xr[0], x1v = xr[1], x2v = xr[2], x3v = xr[3], x4v = xr[4], x5v = xr[5];
        float sA = ba + x0v*wa0 + x1v*wa1 + x2v*wa2 + x3v*wa3 + x4v*wa4 + x5v*wa5;
        float sB = bb + x0v*wb0 + x1v*wb1 + x2v*wb2 + x3v*wb3 + x4v*wb4 + x5v*wb5;
        *reinterpret_cast<uint32_t*>(sb + OFF_ACT + row * ROWB + cp2 * 4) =
            pack_bf2(tanh_fast(sA), tanh_fast(sB));
    }
}

// ---------------- one 64x128x128 layer slice, 2x2 warp tiling ---------------
// warp w: rows [32*(w&1), +32), cols [64*(w>>1), +64). ACT = tanh(ACT @ W^T + b).
// Internal barrier separates in-place MMA reads from stores.
__device__ __forceinline__ void gemm_tanh(char* sb, const float* __restrict__ bias,
                                          int warp, int lane) {
    const int rw = warp & 1, cw = warp >> 1;
    const int g = lane >> 2, tg = lane & 3;
    float acc[2][8][4];
    #pragma unroll
    for (int mt = 0; mt < 2; ++mt)
        #pragma unroll
        for (int t = 0; t < 8; ++t)
            acc[mt][t][0] = acc[mt][t][1] = acc[mt][t][2] = acc[mt][t][3] = 0.f;

    const uint32_t base = smem_u32(sb);
    const int l7 = lane & 7;
    const int rA = (((lane >> 3) & 1) << 3) + l7;
    const int kA = (lane >> 4) << 3;
    uint32_t aaddr0 = base + OFF_ACT + (rw * 32 + rA) * ROWB + kA * 2;
    uint32_t aaddr1 = aaddr0 + 16 * ROWB;
    const int rB = (((lane >> 4) & 1) << 3) + l7;
    const int kB = ((lane >> 3) & 1) << 3;
    uint32_t baddr = base + OFF_W + (cw * 64 + rB) * ROWB + kB * 2;

    #pragma unroll
    for (int kk = 0; kk < 8; ++kk) {
        uint32_t a0, a1, a2, a3, a4, a5, a6, a7;
        ldsm4(a0, a1, a2, a3, aaddr0 + kk * 32);
        ldsm4(a4, a5, a6, a7, aaddr1 + kk * 32);
        #pragma unroll
        for (int np = 0; np < 4; ++np) {
            uint32_t b0, b1, b2, b3;
            ldsm4(b0, b1, b2, b3, baddr + np * (16 * ROWB) + kk * 32);
            mma_bf16(acc[0][2*np][0],   acc[0][2*np][1],   acc[0][2*np][2],   acc[0][2*np][3],
                     a0, a1, a2, a3, b0, b1);
            mma_bf16(acc[0][2*np+1][0], acc[0][2*np+1][1], acc[0][2*np+1][2], acc[0][2*np+1][3],
                     a0, a1, a2, a3, b2, b3);
            mma_bf16(acc[1][2*np][0],   acc[1][2*np][1],   acc[1][2*np][2],   acc[1][2*np][3],
                     a4, a5, a6, a7, b0, b1);
            mma_bf16(acc[1][2*np+1][0], acc[1][2*np+1][1], acc[1][2*np+1][2], acc[1][2*np+1][3],
                     a4, a5, a6, a7, b2, b3);
        }
    }
    __syncthreads();  // all warps' MMA reads of ACT / W complete

    #pragma unroll
    for (int mt = 0; mt < 2; ++mt) {
        char* o0 = sb + OFF_ACT + (rw * 32 + mt * 16 + g) * ROWB + cw * 128;
        #pragma unroll
        for (int t = 0; t < 8; ++t) {
            int c = cw * 64 + t * 8 + tg * 2;
            float b0 = bias[c], b1 = bias[c + 1];
            uint32_t p0 = pack_bf2(tanh_fast(acc[mt][t][0] + b0), tanh_fast(acc[mt][t][1] + b1));
            uint32_t p1 = pack_bf2(tanh_fast(acc[mt][t][2] + b0), tanh_fast(acc[mt][t][3] + b1));
            *reinterpret_cast<uint32_t*>(o0 + (t * 8 + tg * 2) * 2) = p0;
            *reinterpret_cast<uint32_t*>(o0 + 8 * ROWB + (t * 8 + tg * 2) * 2) = p1;
        }
    }
}

__global__ void __launch_bounds__(THREADS, 4)
barriernet_kernel(const float* __restrict__ x,
                  const float* __restrict__ mean_, const float* __restrict__ std_,
                  const float* __restrict__ fc1_w, const float* __restrict__ fc1_b,
                  const float* __restrict__ fc31_w, const float* __restrict__ fc31_b,
                  const float* __restrict__ fc32_w, const float* __restrict__ fc32_b,
                  float* __restrict__ out)
{
    extern __shared__ char sb[];
    const int tid  = threadIdx.x;
    const int warp = tid >> 5;
    const int lane = tid & 31;
    const int row0 = blockIdx.x * ROWS_PER_CTA;

    cp_issue(sb, 0, tid);   // fc21 streams behind staging + fc1

    float* xs  = reinterpret_cast<float*>(sb + OFF_X);
    float* b4  = reinterpret_cast<float*>(sb + OFF_B4);
    float* sml = reinterpret_cast<float*>(sb + OFF_SML);

    for (int i = tid; i < 384; i += THREADS) xs[i] = x[(size_t)row0 * 6 + i];
    for (int i = tid; i < 512; i += THREADS) b4[i] = g_wbias[i >> 7][i & 127];
    if (tid < 3)  sml[tid] = fc31_b[tid];
    if (tid >= 3 && tid < 5) sml[tid] = fc32_b[tid - 3];
    if (tid >= 5 && tid < 11) sml[tid] = std_[tid - 5];
    if (tid >= 11 && tid < 17) sml[tid] = mean_[tid - 11];
    __syncthreads();                 // xs published

    fc1_to_act(sb, fc1_w, fc1_b, xs, tid);
    cp_wait_sync();                  // fc21 staged; ACT published

    // ---- path 1: fc21 -> fcm1 ----
    gemm_tanh(sb, b4 + 0 * 128, warp, lane);
    cp_issue(sb, 1, tid);            // fcm1 (W reads done at gemm's internal barrier)
    cp_wait_sync();
    gemm_tanh(sb, b4 + 1 * 128, warp, lane);
    cp_issue(sb, 2, tid);            // fc22 prefetch overlaps head1 + fc1 recompute
    __syncthreads();                 // publish ACT for cross-warp head reads

    // ---- fc31 head: row = warp*16 + lane (lane<16); weights from global ----
    float d0 = 0.f, d1 = 0.f, d2 = 0.f;
    if (lane < 16) {
        int row = warp * 16 + lane;
        const uint32_t* a = reinterpret_cast<const uint32_t*>(sb + OFF_ACT + row * ROWB);
        d0 = sml[0]; d1 = sml[1]; d2 = sml[2];
        #pragma unroll 8
        for (int i = 0; i < 64; ++i) {
            uint32_t u = a[i];
            float2 av = __bfloat1622float2(*reinterpret_cast<const __nv_bfloat162*>(&u));
            int k = 2 * i;
            float2 wa = __ldg(reinterpret_cast<const float2*>(fc31_w + k));
            float2 wb = __ldg(reinterpret_cast<const float2*>(fc31_w + 128 + k));
            float2 wc = __ldg(reinterpret_cast<const float2*>(fc31_w + 256 + k));
            d0 += av.x * wa.x + av.y * wa.y;
            d1 += av.x * wb.x + av.y * wb.y;
            d2 += av.x * wc.x + av.y * wc.y;
        }
    }
    __syncthreads();                 // head reads done before ACT overwrite

    // ---- path 2: fc1 recompute -> fc22 -> fcm2 ----
    fc1_to_act(sb, fc1_w, fc1_b, xs, tid);
    cp_wait_sync();                  // fc22 staged; ACT published
    gemm_tanh(sb, b4 + 2 * 128, warp, lane);
    cp_issue(sb, 3, tid);            // fcm2
    cp_wait_sync();
    gemm_tanh(sb, b4 + 3 * 128, warp, lane);
    __syncthreads();                 // publish final ACT

    // ---- fc32 head + HOCBF/QP epilogue ----
    if (lane < 16) {
        int row = warp * 16 + lane;
        const uint32_t* a = reinterpret_cast<const uint32_t*>(sb + OFF_ACT + row * ROWB);
        float z0 = sml[3], z1 = sml[4];
        #pragma unroll 8
        for (int i = 0; i < 64; ++i) {
            uint32_t u = a[i];
            float2 av = __bfloat1622float2(*reinterpret_cast<const __nv_bfloat162*>(&u));
            int k = 2 * i;
            float2 wa = __ldg(reinterpret_cast<const float2*>(fc32_w + k));
            float2 wb = __ldg(reinterpret_cast<const float2*>(fc32_w + 128 + k));
            z0 += av.x * wa.x + av.y * wa.y;
            z1 += av.x * wb.x + av.y * wb.y;
        }
        float s0 = 4.f / (1.f + expf(-z0));
        float s1 = 4.f / (1.f + expf(-z1));

        const float* xr = &xs[row * 6];
        float px = xr[0] * sml[5]  + sml[11];
        float vx = xr[1] * sml[6]  + sml[12];
        float py = xr[2] * sml[7]  + sml[13];
        float vy = xr[3] * sml[8]  + sml[14];
        float pz = xr[4] * sml[9]  + sml[15];
        float vz = xr[5] * sml[10] + sml[16];

        float dx = px - 10.f, dy = py - 10.f, dz = pz - 9.f;
        float dx2 = dx*dx, dy2 = dy*dy, dz2 = dz*dz;
        float dx3 = dx2*dx, dy3 = dy2*dy, dz3 = dz2*dz;
        float barrier = dx2*dx2 + dy2*dy2 + dz2*dz2 - 2401.f;   // R^4 = 7^4
        float bdot = 4.f * (dx3*vx + dy3*vy + dz3*vz);
        float Lf2b = 12.f * (dx2*vx*vx + dy2*vy*vy + dz2*vz*vz);
        float Gx = -4.f*dx3, Gy = -4.f*dy3, Gz = -4.f*dz3;
        float hv = Lf2b + (s0 + s1) * bdot + s0 * s1 * barrier;

        float u0 = -d0, u1 = -d1, u2 = -d2;
        float Gu = Gx*u0 + Gy*u1 + Gz*u2;
        float GG = Gx*Gx + Gy*Gy + Gz*Gz;
        float lam = fmaxf(Gu - hv, 0.f) / GG;

        float* o = out + (size_t)(row0 + row) * 3;
        o[0] = u0 - lam * Gx;
        o[1] = u1 - lam * Gy;
        o[2] = u2 - lam * Gz;
    }
}

extern "C" void kernel_launch(void* const* d_in, const int* in_sizes, int n_in,
                              void* d_out, int out_size) {
    const float* x      = (const float*)d_in[0];
    const float* mean_  = (const float*)d_in[1];
    const float* std_   = (const float*)d_in[2];
    const float* fc1_w  = (const float*)d_in[3];
    const float* fc1_b  = (const float*)d_in[4];
    const float* fc21_w = (const float*)d_in[5];
    const float* fc21_b = (const float*)d_in[6];
    const float* fc22_w = (const float*)d_in[7];
    const float* fc22_b = (const float*)d_in[8];
    const float* fcm1_w = (const float*)d_in[9];
    const float* fcm1_b = (const float*)d_in[10];
    const float* fcm2_w = (const float*)d_in[11];
    const float* fcm2_b = (const float*)d_in[12];
    const float* fc31_w = (const float*)d_in[13];
    const float* fc31_b = (const float*)d_in[14];
    const float* fc32_w = (const float*)d_in[15];
    const float* fc32_b = (const float*)d_in[16];
    float* out = (float*)d_out;

    int B = in_sizes[0] / 6;
    int grid = B / ROWS_PER_CTA;

    prep_weights<<<4, 256>>>(fc21_w, fc21_b, fcm1_w, fcm1_b,
                             fc22_w, fc22_b, fcm2_w, fcm2_b);

    cudaFuncSetAttribute(barriernet_kernel,
                         cudaFuncAttributeMaxDynamicSharedMemorySize, SMEM_BYTES);
    barriernet_kernel<<<grid, THREADS, SMEM_BYTES>>>(
        x, mean_, std_, fc1_w, fc1_b, fc31_w, fc31_b, fc32_w, fc32_b, out);
}

// round 10
// speedup vs baseline: 1.1155x; 1.1155x over previous
#include <cuda_runtime.h>
#include <cuda_bf16.h>
#include <cstdint>

// ---------------------------------------------------------------------------
// BarrierNet on GB300, round 10: R3 gemm with 256 rows/CTA.
//   256 thr, 2 CTA/SM, 4x2 warp tiling (32r x 64c per warp), bf16 m16n8k16.
//   Each layer: stage W once (fp32 LDG -> bf16 STS, synchronous, R3-style),
//   then TWO 128-row gemm passes -> weight-stage cost per row halved.
//   fc1 recomputed for path 2 (no H buffer). No prep kernel.
// ---------------------------------------------------------------------------

#define THREADS 256
#define ROWS_PER_CTA 256
#define STRB 136            // bf16 elems per smem row -> bank permutation
#define ROWB (STRB * 2)     // 272 bytes per row

// byte offsets into dynamic smem (total 112768 -> 2 CTAs/SM)
#define OFF_W    0                      // staged weights 128 x 272 (34816)
#define OFF_ACT  34816                  // activations 256 x 272 (69632)
#define OFF_B    104448                 // current layer bias, 128 f32 (512)
#define OFF_X    104960                 // 256*6 f32 (6144)
#define OFF_W31  111104                 // 384 f32 (1536)
#define OFF_SML  112640                 // 17 f32: b31[0..2] b32[3..4] std[5..10] mean[11..16]
#define SMEM_BYTES 112768

__device__ __forceinline__ uint32_t smem_u32(const void* p) {
    uint32_t a;
    asm("{ .reg .u64 t; cvta.to.shared.u64 t, %1; cvt.u32.u64 %0, t; }"
        : "=r"(a) : "l"(p));
    return a;
}

__device__ __forceinline__ void ldsm4(uint32_t& r0, uint32_t& r1, uint32_t& r2, uint32_t& r3,
                                      uint32_t addr) {
    asm volatile("ldmatrix.sync.aligned.m8n8.x4.shared.b16 {%0,%1,%2,%3}, [%4];"
                 : "=r"(r0), "=r"(r1), "=r"(r2), "=r"(r3) : "r"(addr));
}

__device__ __forceinline__ void mma_bf16(float& c0, float& c1, float& c2, float& c3,
                                         uint32_t a0, uint32_t a1, uint32_t a2, uint32_t a3,
                                         uint32_t b0, uint32_t b1) {
    asm volatile(
        "mma.sync.aligned.m16n8k16.row.col.f32.bf16.bf16.f32 "
        "{%0,%1,%2,%3}, {%4,%5,%6,%7}, {%8,%9}, {%0,%1,%2,%3};\n"
        : "+f"(c0), "+f"(c1), "+f"(c2), "+f"(c3)
        : "r"(a0), "r"(a1), "r"(a2), "r"(a3), "r"(b0), "r"(b1));
}

__device__ __forceinline__ uint32_t pack_bf2(float lo, float hi) {
    __nv_bfloat162 h = __floats2bfloat162_rn(lo, hi);
    return *reinterpret_cast<uint32_t*>(&h);
}
__device__ __forceinline__ float tanh_fast(float x) {
    asm("tanh.approx.f32 %0, %0;" : "+f"(x));
    return x;
}

// Stage one 128x128 fp32 weight matrix as bf16 into smem (+ fp32 bias).
// Identical to R3's proven load_w.
__device__ __forceinline__ void load_w(char* sb, const float* __restrict__ Wg,
                                       const float* __restrict__ bg, int tid) {
    __syncthreads();  // previous consumers of OFF_W / ACT done; publishes stores
    const float4* W4 = reinterpret_cast<const float4*>(Wg);
    #pragma unroll
    for (int i = tid; i < 4096; i += THREADS) {
        float4 v = W4[i];
        int row = i >> 5, c4 = i & 31;
        uint2 p = make_uint2(pack_bf2(v.x, v.y), pack_bf2(v.z, v.w));
        *reinterpret_cast<uint2*>(sb + OFF_W + row * ROWB + c4 * 8) = p;
    }
    if (tid < 128) reinterpret_cast<float*>(sb + OFF_B)[tid] = bg[tid];
    __syncthreads();
}

// One 128-row gemm pass at row_base, 4x2 warp tiling, in-place ACT.
// warp w: rows [row_base + 32*(w&3), +32), cols [64*(w>>2), +64).
__device__ __forceinline__ void gemm_pass(char* sb, int row_base, int warp, int lane) {
    const int rw = warp & 3, cw = warp >> 2;
    const int g = lane >> 2, tg = lane & 3;
    float acc[2][8][4];
    #pragma unroll
    for (int mt = 0; mt < 2; ++mt)
        #pragma unroll
        for (int t = 0; t < 8; ++t)
            acc[mt][t][0] = acc[mt][t][1] = acc[mt][t][2] = acc[mt][t][3] = 0.f;

    const uint32_t base = smem_u32(sb);
    const int l7 = lane & 7;
    const int rA = (((lane >> 3) & 1) << 3) + l7;
    const int kA = (lane >> 4) << 3;
    uint32_t aaddr0 = base + OFF_ACT + (row_base + rw * 32 + rA) * ROWB + kA * 2;
    uint32_t aaddr1 = aaddr0 + 16 * ROWB;
    const int rB = (((lane >> 4) & 1) << 3) + l7;
    const int kB = ((lane >> 3) & 1) << 3;
    uint32_t baddr = base + OFF_W + (cw * 64 + rB) * ROWB + kB * 2;

    #pragma unroll
    for (int kk = 0; kk < 8; ++kk) {
        uint32_t a0, a1, a2, a3, a4, a5, a6, a7;
        ldsm4(a0, a1, a2, a3, aaddr0 + kk * 32);
        ldsm4(a4, a5, a6, a7, aaddr1 + kk * 32);
        #pragma unroll
        for (int np = 0; np < 4; ++np) {
            uint32_t b0, b1, b2, b3;
            ldsm4(b0, b1, b2, b3, baddr + np * (16 * ROWB) + kk * 32);
            mma_bf16(acc[0][2*np][0],   acc[0][2*np][1],   acc[0][2*np][2],   acc[0][2*np][3],
                     a0, a1, a2, a3, b0, b1);
            mma_bf16(acc[0][2*np+1][0], acc[0][2*np+1][1], acc[0][2*np+1][2], acc[0][2*np+1][3],
                     a0, a1, a2, a3, b2, b3);
            mma_bf16(acc[1][2*np][0],   acc[1][2*np][1],   acc[1][2*np][2],   acc[1][2*np][3],
                     a4, a5, a6, a7, b0, b1);
            mma_bf16(acc[1][2*np+1][0], acc[1][2*np+1][1], acc[1][2*np+1][2], acc[1][2*np+1][3],
                     a4, a5, a6, a7, b2, b3);
        }
    }
    __syncthreads();  // cross-warp in-place hazard within this 128-row block

    const float* bias = reinterpret_cast<const float*>(sb + OFF_B);
    #pragma unroll
    for (int mt = 0; mt < 2; ++mt) {
        char* o0 = sb + OFF_ACT + (row_base + rw * 32 + mt * 16 + g) * ROWB + cw * 128;
        #pragma unroll
        for (int t = 0; t < 8; ++t) {
            int c = cw * 64 + t * 8 + tg * 2;
            float b0 = bias[c], b1 = bias[c + 1];
            uint32_t p0 = pack_bf2(tanh_fast(acc[mt][t][0] + b0), tanh_fast(acc[mt][t][1] + b1));
            uint32_t p1 = pack_bf2(tanh_fast(acc[mt][t][2] + b0), tanh_fast(acc[mt][t][3] + b1));
            *reinterpret_cast<uint32_t*>(o0 + (t * 8 + tg * 2) * 2) = p0;
            *reinterpret_cast<uint32_t*>(o0 + 8 * ROWB + (t * 8 + tg * 2) * 2) = p1;
        }
    }
    // No trailing barrier: next pass touches a disjoint 128-row block; the
    // next load_w / explicit barrier publishes these stores before reuse.
}

// fc1 (K=6) + tanh -> ACT rows 0..255 (bf16). Each thread: 2 cols x 64 rows.
__device__ __forceinline__ void fc1_to_act(char* sb, const float* __restrict__ fc1_w,
                                           const float* __restrict__ fc1_b,
                                           const float* __restrict__ xs, int tid) {
    const int cp2 = tid & 63;          // column pair 0..63
    const int rq  = tid >> 6;          // row quarter 0..3 (64 rows each)
    const int c0 = 2 * cp2;
    const float* wA = fc1_w + c0 * 6;
    const float* wB = wA + 6;
    float wa0 = wA[0], wa1 = wA[1], wa2 = wA[2], wa3 = wA[3], wa4 = wA[4], wa5 = wA[5];
    float wb0 = wB[0], wb1 = wB[1], wb2 = wB[2], wb3 = wB[3], wb4 = wB[4], wb5 = wB[5];
    float ba = fc1_b[c0], bb = fc1_b[c0 + 1];
    #pragma unroll 8
    for (int rr = 0; rr < 64; ++rr) {
        int row = rq * 64 + rr;
        const float* xr = &xs[row * 6];
        float x0v = xr[0], x1v = xr[1], x2v = xr[2], x3v = xr[3], x4v = xr[4], x5v = xr[5];
        float sA = ba + x0v*wa0 + x1v*wa1 + x2v*wa2 + x3v*wa3 + x4v*wa4 + x5v*wa5;
        float sB = bb + x0v*wb0 + x1v*wb1 + x2v*wb2 + x3v*wb3 + x4v*wb4 + x5v*wb5;
        *reinterpret_cast<uint32_t*>(sb + OFF_ACT + row * ROWB + cp2 * 4) =
            pack_bf2(tanh_fast(sA), tanh_fast(sB));
    }
}

__global__ void __launch_bounds__(THREADS, 2)
barriernet_kernel(const float* __restrict__ x,
                  const float* __restrict__ mean_, const float* __restrict__ std_,
                  const float* __restrict__ fc1_w, const float* __restrict__ fc1_b,
                  const float* __restrict__ fc21_w, const float* __restrict__ fc21_b,
                  const float* __restrict__ fc22_w, const float* __restrict__ fc22_b,
                  const float* __restrict__ fcm1_w, const float* __restrict__ fcm1_b,
                  const float* __restrict__ fcm2_w, const float* __restrict__ fcm2_b,
                  const float* __restrict__ fc31_w, const float* __restrict__ fc31_b,
                  const float* __restrict__ fc32_w, const float* __restrict__ fc32_b,
                  float* __restrict__ out)
{
    extern __shared__ char sb[];
    const int tid  = threadIdx.x;
    const int warp = tid >> 5;
    const int lane = tid & 31;
    const int row0 = blockIdx.x * ROWS_PER_CTA;

    float* xs   = reinterpret_cast<float*>(sb + OFF_X);
    float* w31s = reinterpret_cast<float*>(sb + OFF_W31);
    float* sml  = reinterpret_cast<float*>(sb + OFF_SML);

    for (int i = tid; i < 1536; i += THREADS) xs[i] = x[(size_t)row0 * 6 + i];
    for (int i = tid; i < 384; i += THREADS) w31s[i] = fc31_w[i];
    if (tid < 3)  sml[tid] = fc31_b[tid];
    if (tid >= 3 && tid < 5) sml[tid] = fc32_b[tid - 3];
    if (tid >= 5 && tid < 11) sml[tid] = std_[tid - 5];
    if (tid >= 11 && tid < 17) sml[tid] = mean_[tid - 11];
    __syncthreads();                  // xs published

    // ---- fc1 -> ACT (path 1 input) ----
    fc1_to_act(sb, fc1_w, fc1_b, xs, tid);

    // ---- path 1: fc21 -> fcm1 ----
    load_w(sb, fc21_w, fc21_b, tid);  // barriers also publish ACT
    gemm_pass(sb, 0, warp, lane);
    gemm_pass(sb, 128, warp, lane);
    load_w(sb, fcm1_w, fcm1_b, tid);
    gemm_pass(sb, 0, warp, lane);
    gemm_pass(sb, 128, warp, lane);
    __syncthreads();                  // publish ACT for cross-warp head reads

    // ---- fc31 head: row = warp*32 + lane (full warp), kept in registers ----
    float d0, d1, d2;
    {
        int row = warp * 32 + lane;
        const uint32_t* a = reinterpret_cast<const uint32_t*>(sb + OFF_ACT + row * ROWB);
        d0 = sml[0]; d1 = sml[1]; d2 = sml[2];
        #pragma unroll 8
        for (int i = 0; i < 64; ++i) {
            uint32_t u = a[i];
            float2 av = __bfloat1622float2(*reinterpret_cast<const __nv_bfloat162*>(&u));
            int k = 2 * i;
            d0 += av.x * w31s[k]       + av.y * w31s[k + 1];
            d1 += av.x * w31s[128 + k] + av.y * w31s[128 + k + 1];
            d2 += av.x * w31s[256 + k] + av.y * w31s[256 + k + 1];
        }
    }
    __syncthreads();                  // head reads done before ACT overwrite

    // ---- path 2: fc1 recompute -> fc22 -> fcm2 ----
    fc1_to_act(sb, fc1_w, fc1_b, xs, tid);
    load_w(sb, fc22_w, fc22_b, tid);
    gemm_pass(sb, 0, warp, lane);
    gemm_pass(sb, 128, warp, lane);
    load_w(sb, fcm2_w, fcm2_b, tid);
    gemm_pass(sb, 0, warp, lane);
    gemm_pass(sb, 128, warp, lane);
    __syncthreads();                  // publish final ACT

    // ---- fc32 head + HOCBF/QP epilogue: row = warp*32 + lane ----
    {
        int row = warp * 32 + lane;
        const uint32_t* a = reinterpret_cast<const uint32_t*>(sb + OFF_ACT + row * ROWB);
        float z0 = sml[3], z1 = sml[4];
        #pragma unroll 8
        for (int i = 0; i < 64; ++i) {
            uint32_t u = a[i];
            float2 av = __bfloat1622float2(*reinterpret_cast<const __nv_bfloat162*>(&u));
            int k = 2 * i;
            float2 wa = __ldg(reinterpret_cast<const float2*>(fc32_w + k));
            float2 wb = __ldg(reinterpret_cast<const float2*>(fc32_w + 128 + k));
            z0 += av.x * wa.x + av.y * wa.y;
            z1 += av.x * wb.x + av.y * wb.y;
        }
        float s0 = 4.f / (1.f + expf(-z0));
        float s1 = 4.f / (1.f + expf(-z1));

        const float* xr = &xs[row * 6];
        float px = xr[0] * sml[5]  + sml[11];
        float vx = xr[1] * sml[6]  + sml[12];
        float py = xr[2] * sml[7]  + sml[13];
        float vy = xr[3] * sml[8]  + sml[14];
        float pz = xr[4] * sml[9]  + sml[15];
        float vz = xr[5] * sml[10] + sml[16];

        float dx = px - 10.f, dy = py - 10.f, dz = pz - 9.f;
        float dx2 = dx*dx, dy2 = dy*dy, dz2 = dz*dz;
        float dx3 = dx2*dx, dy3 = dy2*dy, dz3 = dz2*dz;
        float barrier = dx2*dx2 + dy2*dy2 + dz2*dz2 - 2401.f;   // R^4 = 7^4
        float bdot = 4.f * (dx3*vx + dy3*vy + dz3*vz);
        float Lf2b = 12.f * (dx2*vx*vx + dy2*vy*vy + dz2*vz*vz);
        float Gx = -4.f*dx3, Gy = -4.f*dy3, Gz = -4.f*dz3;
        float hv = Lf2b + (s0 + s1) * bdot + s0 * s1 * barrier;

        float u0 = -d0, u1 = -d1, u2 = -d2;
        float Gu = Gx*u0 + Gy*u1 + Gz*u2;
        float GG = Gx*Gx + Gy*Gy + Gz*Gz;
        float lam = fmaxf(Gu - hv, 0.f) / GG;

        float* o = out + (size_t)(row0 + row) * 3;
        o[0] = u0 - lam * Gx;
        o[1] = u1 - lam * Gy;
        o[2] = u2 - lam * Gz;
    }
}

extern "C" void kernel_launch(void* const* d_in, const int* in_sizes, int n_in,
                              void* d_out, int out_size) {
    const float* x      = (const float*)d_in[0];
    const float* mean_  = (const float*)d_in[1];
    const float* std_   = (const float*)d_in[2];
    const float* fc1_w  = (const float*)d_in[3];
    const float* fc1_b  = (const float*)d_in[4];
    const float* fc21_w = (const float*)d_in[5];
    const float* fc21_b = (const float*)d_in[6];
    const float* fc22_w = (const float*)d_in[7];
    const float* fc22_b = (const float*)d_in[8];
    const float* fcm1_w = (const float*)d_in[9];
    const float* fcm1_b = (const float*)d_in[10];
    const float* fcm2_w = (const float*)d_in[11];
    const float* fcm2_b = (const float*)d_in[12];
    const float* fc31_w = (const float*)d_in[13];
    const float* fc31_b = (const float*)d_in[14];
    const float* fc32_w = (const float*)d_in[15];
    const float* fc32_b = (const float*)d_in[16];
    float* out = (float*)d_out;

    int B = in_sizes[0] / 6;
    int grid = B / ROWS_PER_CTA;

    cudaFuncSetAttribute(barriernet_kernel,
                         cudaFuncAttributeMaxDynamicSharedMemorySize, SMEM_BYTES);
    barriernet_kernel<<<grid, THREADS, SMEM_BYTES>>>(
        x, mean_, std_, fc1_w, fc1_b, fc21_w, fc21_b, fc22_w, fc22_b,
        fcm1_w, fcm1_b, fcm2_w, fcm2_b, fc31_w, fc31_b, fc32_w, fc32_b, out);
}